// round 9
// baseline (speedup 1.0000x reference)
#include <cuda_runtime.h>
#include <math.h>

#define H    1024
#define V    50257
#define S    4096
#define G3   3072
#define NB   148
#define NT   1024
#define NWARP (NB * 32)
#define ROWS_PB 340            // ceil(V/NB)
#define NA   24                // attention blocks
#define ACH  171               // ceil(S/NA)
#define VICH 43                // ceil(H/NA) rows of Wattn per attn block
#define NTILES 1571            // ceil(V/32) first-half row tiles

// ---------------- global scratch ----------------
__device__ float g_gi0[G3];
__device__ float g_gh0[G3];
__device__ float g_gi1[G3];
__device__ float g_gh1[G3];
__device__ float g_v[H];
__device__ float g_energ[S];
__device__ float g_ctx[H];
__device__ float g_lhalf[V + 32];         // W_out[:, :H] @ h1
__device__ float g_part[2 * NB];
__device__ unsigned g_q;                  // work queue counter
__device__ unsigned g_count;
__device__ volatile unsigned g_epoch;
__device__ unsigned g_acount;             // attention subgroup barrier
__device__ volatile unsigned g_aepoch;

// ---------------- barriers ----------------
__device__ __forceinline__ void gsync() {
    __syncthreads();
    if (threadIdx.x == 0) {
        __threadfence();
        unsigned e = g_epoch;
        if (atomicAdd(&g_count, 1) == (unsigned)(gridDim.x - 1)) {
            g_count = 0;
            __threadfence();
            g_epoch = e + 1;
        } else {
            while (g_epoch == e) __nanosleep(32);
        }
        __threadfence();
    }
    __syncthreads();
}

__device__ __forceinline__ void async_bar() {   // among NA attention blocks
    __syncthreads();
    if (threadIdx.x == 0) {
        __threadfence();
        unsigned e = g_aepoch;
        if (atomicAdd(&g_acount, 1) == (unsigned)(NA - 1)) {
            g_acount = 0;
            __threadfence();
            g_aepoch = e + 1;
        } else {
            while (g_aepoch == e) __nanosleep(32);
        }
        __threadfence();
    }
    __syncthreads();
}

__device__ __forceinline__ float sigmoidf_(float x) {
    return 1.f / (1.f + __expf(-x));
}

// warp dot: w global, x shared; n4 in {256, 512}
__device__ __forceinline__ float wdot(const float4* __restrict__ w,
                                      const float4* __restrict__ x,
                                      int n4, int lane) {
    float s0 = 0.f, s1 = 0.f, s2 = 0.f, s3 = 0.f;
#pragma unroll 4
    for (int i = lane; i < n4; i += 128) {
        float4 a0 = w[i];        float4 b0 = x[i];
        float4 a1 = w[i + 32];   float4 b1 = x[i + 32];
        float4 a2 = w[i + 64];   float4 b2 = x[i + 64];
        float4 a3 = w[i + 96];   float4 b3 = x[i + 96];
        s0 = fmaf(a0.x, b0.x, fmaf(a0.y, b0.y, fmaf(a0.z, b0.z, fmaf(a0.w, b0.w, s0))));
        s1 = fmaf(a1.x, b1.x, fmaf(a1.y, b1.y, fmaf(a1.z, b1.z, fmaf(a1.w, b1.w, s1))));
        s2 = fmaf(a2.x, b2.x, fmaf(a2.y, b2.y, fmaf(a2.z, b2.z, fmaf(a2.w, b2.w, s2))));
        s3 = fmaf(a3.x, b3.x, fmaf(a3.y, b3.y, fmaf(a3.z, b3.z, fmaf(a3.w, b3.w, s3))));
    }
    float s = (s0 + s1) + (s2 + s3);
#pragma unroll
    for (int o = 16; o; o >>= 1) s += __shfl_xor_sync(0xffffffffu, s, o);
    return s;
}

__global__ void __launch_bounds__(NT, 1)
decoder_kernel(const int* __restrict__ word, const float* __restrict__ lctx,
               const float* __restrict__ lh, const float* __restrict__ enc,
               const float* __restrict__ emb,
               const float* __restrict__ Wih0, const float* __restrict__ Whh0,
               const float* __restrict__ bih0, const float* __restrict__ bhh0,
               const float* __restrict__ Wih1, const float* __restrict__ Whh1,
               const float* __restrict__ bih1, const float* __restrict__ bhh1,
               const float* __restrict__ Wattn, const float* __restrict__ Wout,
               const float* __restrict__ bout, float* __restrict__ out) {
    __shared__ float sh_in[2 * H];
    __shared__ float sh_lh[2 * H];
    __shared__ float sh_h0[H];            // h0; later stages v for attention
    __shared__ float sh_xcat[2 * H];      // [h1 ; ctx]
    __shared__ float sh_logit[ROWS_PB];
    __shared__ float sh_a[ACH];
    __shared__ float sh_red[32];
    __shared__ float sh_bc[2];
    __shared__ int   sh_tile;

    const int t = threadIdx.x;
    const int lane = t & 31;
    const int wid = t >> 5;
    const int b = blockIdx.x;
    const int gw = b * 32 + wid;

    // stage inputs; block 0 resets queue + accumulators (ordered by gsync1)
    {
        int w0 = word[0];
        sh_in[t]     = emb[(size_t)w0 * H + t];
        sh_in[H + t] = lctx[t];
        sh_lh[t]     = lh[t];
        sh_lh[H + t] = lh[H + t];
    }
    if (b == 0) {
        g_v[t] = 0.f;
        g_ctx[t] = 0.f;
        if (t == 0) g_q = 0;
    }
    __syncthreads();

    // ---------- phase 1: gi0 (dot 2048) + gh0 + gh1 (dot 1024) ----------
    for (int r = gw; r < 3 * G3; r += NWARP) {
        if (r < G3) {
            float s = wdot((const float4*)(Wih0 + (size_t)r * 2 * H),
                           (const float4*)sh_in, 512, lane);
            if (!lane) g_gi0[r] = s + bih0[r];
        } else if (r < 2 * G3) {
            int rr = r - G3;
            float s = wdot((const float4*)(Whh0 + (size_t)rr * H),
                           (const float4*)sh_lh, 256, lane);
            if (!lane) g_gh0[rr] = s + bhh0[rr];
        } else {
            int rr = r - 2 * G3;
            float s = wdot((const float4*)(Whh1 + (size_t)rr * H),
                           (const float4*)(sh_lh + H), 256, lane);
            if (!lane) g_gh1[rr] = s + bhh1[rr];
        }
    }
    gsync();   // barrier 1

    // ---------- phase 2: h0 recompute (local); gi1 = W_ih1 @ h0 ----------
    {
        float r_ = sigmoidf_(g_gi0[t] + g_gh0[t]);
        float z  = sigmoidf_(g_gi0[H + t] + g_gh0[H + t]);
        float n  = tanhf(g_gi0[2 * H + t] + r_ * g_gh0[2 * H + t]);
        float h  = (1.f - z) * n + z * sh_lh[t];
        sh_h0[t] = h;
        if (b == 0) out[V + H + t] = h;   // hidden[0]
    }
    __syncthreads();
    if (gw < G3) {
        float s = wdot((const float4*)(Wih1 + (size_t)gw * H),
                       (const float4*)sh_h0, 256, lane);
        if (!lane) g_gi1[gw] = s + bih1[gw];
    }
    gsync();   // barrier 2

    // ---------- phase 3: h1 recompute (local, no barrier needed after) ----
    {
        float r_ = sigmoidf_(g_gi1[t] + g_gh1[t]);
        float z  = sigmoidf_(g_gi1[H + t] + g_gh1[H + t]);
        float n  = tanhf(g_gi1[2 * H + t] + r_ * g_gh1[2 * H + t]);
        float h  = (1.f - z) * n + z * sh_lh[H + t];
        sh_xcat[t] = h;
        if (b == 0) out[V + 2 * H + t] = h; // hidden[1]
    }
    __syncthreads();

    // ---------- phase 4 (split): attention on blocks 0..NA-1 --------------
    if (b < NA) {
        // v partials: rows [b*VICH, b*VICH+VICH)
        {
            float acc = 0.f;
            int i0 = b * VICH;
#pragma unroll 4
            for (int k = 0; k < VICH; k++) {
                int i = i0 + k;
                if (i < H) acc = fmaf(Wattn[(size_t)i * H + t], sh_xcat[i], acc);
            }
            atomicAdd(&g_v[t], acc);
        }
        async_bar();                       // v complete among NA blocks

        sh_h0[t] = g_v[t];                 // stage v
        __syncthreads();
        for (int r = b * 32 + wid; r < S; r += NA * 32) {
            float s = wdot((const float4*)(enc + (size_t)r * H),
                           (const float4*)sh_h0, 256, lane);
            if (!lane) g_energ[r] = s;
        }
        async_bar();                       // energies complete

        // softmax (redundant per attn block)
        float m = -INFINITY;
        for (int i = t; i < S; i += NT) m = fmaxf(m, g_energ[i]);
#pragma unroll
        for (int o = 16; o; o >>= 1) m = fmaxf(m, __shfl_xor_sync(0xffffffffu, m, o));
        if (!lane) sh_red[wid] = m;
        __syncthreads();
        if (wid == 0) {
            m = sh_red[lane];
#pragma unroll
            for (int o = 16; o; o >>= 1) m = fmaxf(m, __shfl_xor_sync(0xffffffffu, m, o));
            if (!lane) sh_bc[0] = m;
        }
        __syncthreads();
        float bmax = sh_bc[0];
        float sum = 0.f;
        for (int i = t; i < S; i += NT) sum += __expf(g_energ[i] - bmax);
#pragma unroll
        for (int o = 16; o; o >>= 1) sum += __shfl_xor_sync(0xffffffffu, sum, o);
        if (!lane) sh_red[wid] = sum;
        __syncthreads();
        if (wid == 0) {
            sum = sh_red[lane];
#pragma unroll
            for (int o = 16; o; o >>= 1) sum += __shfl_xor_sync(0xffffffffu, sum, o);
            if (!lane) sh_bc[1] = sum;
        }
        __syncthreads();
        float inv = 1.f / sh_bc[1];
        int s0 = b * ACH;
        int nch = min(ACH, S - s0);
        if (t < nch) {
            float a = __expf(g_energ[s0 + t] - bmax) * inv;
            sh_a[t] = a;
            out[V + 3 * H + s0 + t] = a;   // attn_weights
        }
        __syncthreads();
        // ctx partials over this block's s-chunk
        {
            float acc = 0.f;
#pragma unroll 8
            for (int k = 0; k < ACH; k++) {
                if (k < nch) acc = fmaf(sh_a[k], enc[(size_t)(s0 + k) * H + t], acc);
            }
            atomicAdd(&g_ctx[t], acc);
        }
    }

    // ---------- phase 4 (all blocks eventually): first-half logits queue --
    // lhalf[r] = W_out[r, 0:H] . h1   (h1 in sh_xcat[0:H])
    for (;;) {
        if (t == 0) sh_tile = (int)atomicAdd(&g_q, 1u);
        __syncthreads();
        int tile = sh_tile;
        __syncthreads();
        if (tile >= NTILES) break;
        int r = tile * 32 + wid;
        if (r < V) {
            float s = wdot((const float4*)(Wout + (size_t)r * 2 * H),
                           (const float4*)sh_xcat, 256, lane);
            if (!lane) g_lhalf[r] = s;
        }
    }
    gsync();   // barrier 3: lhalf + ctx ready

    // ---------- phase 5: second-half logits + block LSE -------------------
    sh_xcat[H + t] = g_ctx[t];
    if (b == 0) out[V + t] = g_ctx[t];    // context
    __syncthreads();
    const int base = b * ROWS_PB;
    const int nrows = min(ROWS_PB, V - base);
    for (int rl = wid; rl < nrows; rl += 32) {
        int r = base + rl;
        // second half of the row starts at float offset H (columns H..2H-1)
        float s = wdot((const float4*)(Wout + (size_t)r * 2 * H + H),
                       (const float4*)(sh_xcat + H), 256, lane);
        if (!lane) sh_logit[rl] = s + g_lhalf[r] + bout[r];
    }
    __syncthreads();
    {
        float m = -INFINITY;
        for (int i = t; i < nrows; i += NT) m = fmaxf(m, sh_logit[i]);
#pragma unroll
        for (int o = 16; o; o >>= 1) m = fmaxf(m, __shfl_xor_sync(0xffffffffu, m, o));
        if (!lane) sh_red[wid] = m;
        __syncthreads();
        if (wid == 0) {
            m = sh_red[lane];
#pragma unroll
            for (int o = 16; o; o >>= 1) m = fmaxf(m, __shfl_xor_sync(0xffffffffu, m, o));
            if (!lane) sh_bc[0] = m;
        }
        __syncthreads();
        float bmax = sh_bc[0];
        float sum = 0.f;
        for (int i = t; i < nrows; i += NT) sum += __expf(sh_logit[i] - bmax);
#pragma unroll
        for (int o = 16; o; o >>= 1) sum += __shfl_xor_sync(0xffffffffu, sum, o);
        if (!lane) sh_red[wid] = sum;
        __syncthreads();
        if (wid == 0) {
            sum = sh_red[lane];
#pragma unroll
            for (int o = 16; o; o >>= 1) sum += __shfl_xor_sync(0xffffffffu, sum, o);
            if (!lane) { g_part[2 * b] = bmax; g_part[2 * b + 1] = sum; }
        }
    }
    gsync();   // barrier 4

    // ---------- phase 6: merge LSE; write log_softmax ---------------------
    {
        if (wid == 0) {
            float m = -INFINITY, sacc = 0.f;
            for (int i = lane; i < NB; i += 32) {
                float mi = g_part[2 * i], si = g_part[2 * i + 1];
                float mn = fmaxf(m, mi);
                sacc = sacc * __expf(m - mn) + si * __expf(mi - mn);
                m = mn;
            }
#pragma unroll
            for (int o = 16; o; o >>= 1) {
                float mo = __shfl_xor_sync(0xffffffffu, m, o);
                float so = __shfl_xor_sync(0xffffffffu, sacc, o);
                float mn = fmaxf(m, mo);
                sacc = sacc * __expf(m - mn) + so * __expf(mo - mn);
                m = mn;
            }
            if (!lane) { sh_bc[0] = m; sh_bc[1] = logf(sacc); }
        }
        __syncthreads();
        float mm = sh_bc[0], ls = sh_bc[1];
        for (int i = t; i < nrows; i += NT)
            out[base + i] = sh_logit[i] - mm - ls;
    }
}

// ---------------- launch ----------------
extern "C" void kernel_launch(void* const* d_in, const int* in_sizes, int n_in,
                              void* d_out, int out_size) {
    const int*   word  = (const int*)  d_in[0];
    const float* lctx  = (const float*)d_in[1];
    const float* lh    = (const float*)d_in[2];
    const float* enc   = (const float*)d_in[3];
    const float* emb   = (const float*)d_in[4];
    const float* Wih0  = (const float*)d_in[5];
    const float* Whh0  = (const float*)d_in[6];
    const float* bih0  = (const float*)d_in[7];
    const float* bhh0  = (const float*)d_in[8];
    const float* Wih1  = (const float*)d_in[9];
    const float* Whh1  = (const float*)d_in[10];
    const float* bih1  = (const float*)d_in[11];
    const float* bhh1  = (const float*)d_in[12];
    const float* Wattn = (const float*)d_in[13];
    // d_in[14] = b_attn: cancels in softmax
    const float* Wout  = (const float*)d_in[15];
    const float* bout  = (const float*)d_in[16];
    float* out = (float*)d_out;

    decoder_kernel<<<NB, NT>>>(word, lctx, lh, enc, emb,
                               Wih0, Whh0, bih0, bhh0,
                               Wih1, Whh1, bih1, bhh1,
                               Wattn, Wout, bout, out);
}

// round 11
// speedup vs baseline: 1.0689x; 1.0689x over previous
#include <cuda_runtime.h>
#include <math.h>

#define H    1024
#define V    50257
#define S    4096
#define G3   3072
#define NB   148
#define NT   1024
#define NWARP (NB * 32)
#define ROWS_PB 340            // ceil(V/NB)
#define SCH 28                 // ceil(S/NB)
#define ICH 7                  // ceil(H/NB)

// ---------------- global scratch ----------------
__device__ float g_gi0[G3];
__device__ float g_gh0[G3];
__device__ float g_gi1[G3];
__device__ float g_gh1[G3];
__device__ float g_v[H];
__device__ float g_energ[S];
__device__ float g_ctx[H];
__device__ float g_part[2 * NB];
__device__ unsigned g_count;
__device__ volatile unsigned g_epoch;

// ---------------- software grid barrier ----------------
__device__ __forceinline__ void gsync() {
    __syncthreads();
    if (threadIdx.x == 0) {
        __threadfence();
        unsigned e = g_epoch;
        if (atomicAdd(&g_count, 1) == (unsigned)(gridDim.x - 1)) {
            g_count = 0;
            __threadfence();
            g_epoch = e + 1;
        } else {
            while (g_epoch == e) __nanosleep(32);
        }
        __threadfence();
    }
    __syncthreads();
}

__device__ __forceinline__ float sigmoidf_(float x) {
    return 1.f / (1.f + __expf(-x));
}

// 1-row warp dot (4-stream), n4 multiple of 128
__device__ __forceinline__ float wdot(const float4* __restrict__ w,
                                      const float4* __restrict__ x,
                                      int n4, int lane) {
    float s0 = 0.f, s1 = 0.f, s2 = 0.f, s3 = 0.f;
#pragma unroll 4
    for (int i = lane; i < n4; i += 128) {
        float4 a0 = w[i];        float4 b0 = x[i];
        float4 a1 = w[i + 32];   float4 b1 = x[i + 32];
        float4 a2 = w[i + 64];   float4 b2 = x[i + 64];
        float4 a3 = w[i + 96];   float4 b3 = x[i + 96];
        s0 = fmaf(a0.x, b0.x, fmaf(a0.y, b0.y, fmaf(a0.z, b0.z, fmaf(a0.w, b0.w, s0))));
        s1 = fmaf(a1.x, b1.x, fmaf(a1.y, b1.y, fmaf(a1.z, b1.z, fmaf(a1.w, b1.w, s1))));
        s2 = fmaf(a2.x, b2.x, fmaf(a2.y, b2.y, fmaf(a2.z, b2.z, fmaf(a2.w, b2.w, s2))));
        s3 = fmaf(a3.x, b3.x, fmaf(a3.y, b3.y, fmaf(a3.z, b3.z, fmaf(a3.w, b3.w, s3))));
    }
    float s = (s0 + s1) + (s2 + s3);
#pragma unroll
    for (int o = 16; o; o >>= 1) s += __shfl_xor_sync(0xffffffffu, s, o);
    return s;
}

// 2-row warp dot, 2-way i-unroll: 4 LDG + 2 LDS per iter, MLP 4/lane
__device__ __forceinline__ void wdot2(const float4* __restrict__ w0,
                                      const float4* __restrict__ w1,
                                      const float4* __restrict__ x,
                                      int n4, int lane,
                                      float& r0, float& r1) {
    float s00 = 0.f, s01 = 0.f, s10 = 0.f, s11 = 0.f;
    for (int i = lane; i < n4; i += 64) {
        float4 xv0 = x[i];
        float4 xv1 = x[i + 32];
        float4 a00 = w0[i];
        float4 a10 = w1[i];
        float4 a01 = w0[i + 32];
        float4 a11 = w1[i + 32];
        s00 = fmaf(a00.x, xv0.x, fmaf(a00.y, xv0.y, fmaf(a00.z, xv0.z, fmaf(a00.w, xv0.w, s00))));
        s10 = fmaf(a10.x, xv0.x, fmaf(a10.y, xv0.y, fmaf(a10.z, xv0.z, fmaf(a10.w, xv0.w, s10))));
        s01 = fmaf(a01.x, xv1.x, fmaf(a01.y, xv1.y, fmaf(a01.z, xv1.z, fmaf(a01.w, xv1.w, s01))));
        s11 = fmaf(a11.x, xv1.x, fmaf(a11.y, xv1.y, fmaf(a11.z, xv1.z, fmaf(a11.w, xv1.w, s11))));
    }
    float a = s00 + s01;
    float b = s10 + s11;
#pragma unroll
    for (int o = 16; o; o >>= 1) {
        a += __shfl_xor_sync(0xffffffffu, a, o);
        b += __shfl_xor_sync(0xffffffffu, b, o);
    }
    r0 = a; r1 = b;
}

// 8-row warp dot: 8 LDG + 1 LDS per iter, MLP 8/lane
__device__ __forceinline__ void wdot8(const float4* wp0, const float4* wp1,
                                      const float4* wp2, const float4* wp3,
                                      const float4* wp4, const float4* wp5,
                                      const float4* wp6, const float4* wp7,
                                      const float4* __restrict__ x,
                                      int n4, int lane, float s[8]) {
#pragma unroll
    for (int k = 0; k < 8; k++) s[k] = 0.f;
    for (int i = lane; i < n4; i += 32) {
        float4 xv = x[i];
        float4 a0 = wp0[i]; float4 a1 = wp1[i];
        float4 a2 = wp2[i]; float4 a3 = wp3[i];
        float4 a4 = wp4[i]; float4 a5 = wp5[i];
        float4 a6 = wp6[i]; float4 a7 = wp7[i];
        s[0] = fmaf(a0.x, xv.x, fmaf(a0.y, xv.y, fmaf(a0.z, xv.z, fmaf(a0.w, xv.w, s[0]))));
        s[1] = fmaf(a1.x, xv.x, fmaf(a1.y, xv.y, fmaf(a1.z, xv.z, fmaf(a1.w, xv.w, s[1]))));
        s[2] = fmaf(a2.x, xv.x, fmaf(a2.y, xv.y, fmaf(a2.z, xv.z, fmaf(a2.w, xv.w, s[2]))));
        s[3] = fmaf(a3.x, xv.x, fmaf(a3.y, xv.y, fmaf(a3.z, xv.z, fmaf(a3.w, xv.w, s[3]))));
        s[4] = fmaf(a4.x, xv.x, fmaf(a4.y, xv.y, fmaf(a4.z, xv.z, fmaf(a4.w, xv.w, s[4]))));
        s[5] = fmaf(a5.x, xv.x, fmaf(a5.y, xv.y, fmaf(a5.z, xv.z, fmaf(a5.w, xv.w, s[5]))));
        s[6] = fmaf(a6.x, xv.x, fmaf(a6.y, xv.y, fmaf(a6.z, xv.z, fmaf(a6.w, xv.w, s[6]))));
        s[7] = fmaf(a7.x, xv.x, fmaf(a7.y, xv.y, fmaf(a7.z, xv.z, fmaf(a7.w, xv.w, s[7]))));
    }
#pragma unroll
    for (int k = 0; k < 8; k++) {
#pragma unroll
        for (int o = 16; o; o >>= 1) s[k] += __shfl_xor_sync(0xffffffffu, s[k], o);
    }
}

__global__ void __launch_bounds__(NT, 1)
decoder_kernel(const int* __restrict__ word, const float* __restrict__ lctx,
               const float* __restrict__ lh, const float* __restrict__ enc,
               const float* __restrict__ emb,
               const float* __restrict__ Wih0, const float* __restrict__ Whh0,
               const float* __restrict__ bih0, const float* __restrict__ bhh0,
               const float* __restrict__ Wih1, const float* __restrict__ Whh1,
               const float* __restrict__ bih1, const float* __restrict__ bhh1,
               const float* __restrict__ Wattn, const float* __restrict__ Wout,
               const float* __restrict__ bout, float* __restrict__ out) {
    __shared__ float sh_in[2 * H];
    __shared__ float sh_lh[2 * H];
    __shared__ float sh_h0[H];            // h0; later stages v
    __shared__ float sh_xcat[2 * H];      // [h1 ; ctx]
    __shared__ float sh_logit[ROWS_PB];
    __shared__ float sh_a[SCH];
    __shared__ float sh_red[32];
    __shared__ float sh_bc[2];

    const int t = threadIdx.x;
    const int lane = t & 31;
    const int wid = t >> 5;
    const int b = blockIdx.x;
    const int gw = b * 32 + wid;

    {
        int w0 = word[0];
        sh_in[t]     = emb[(size_t)w0 * H + t];
        sh_in[H + t] = lctx[t];
        sh_lh[t]     = lh[t];
        sh_lh[H + t] = lh[H + t];
    }
    if (b == 0) { g_v[t] = 0.f; g_ctx[t] = 0.f; }
    __syncthreads();

    // ---------- phase 1: gi0/gh0/gh1 as 2-row units, interleaved mod 3 ----
    // units: 1536 per segment, 4608 total (< 4736 warps, one pass)
    if (gw < 4608) {
        int type = gw % 3;
        int idx  = gw / 3;          // 0..1535
        int r0 = 2 * idx;
        float v0, v1;
        if (type == 0) {
            wdot2((const float4*)(Wih0 + (size_t)r0 * 2 * H),
                  (const float4*)(Wih0 + (size_t)(r0 + 1) * 2 * H),
                  (const float4*)sh_in, 512, lane, v0, v1);
            if (!lane) { g_gi0[r0] = v0 + bih0[r0]; g_gi0[r0 + 1] = v1 + bih0[r0 + 1]; }
        } else if (type == 1) {
            wdot2((const float4*)(Whh0 + (size_t)r0 * H),
                  (const float4*)(Whh0 + (size_t)(r0 + 1) * H),
                  (const float4*)sh_lh, 256, lane, v0, v1);
            if (!lane) { g_gh0[r0] = v0 + bhh0[r0]; g_gh0[r0 + 1] = v1 + bhh0[r0 + 1]; }
        } else {
            wdot2((const float4*)(Whh1 + (size_t)r0 * H),
                  (const float4*)(Whh1 + (size_t)(r0 + 1) * H),
                  (const float4*)(sh_lh + H), 256, lane, v0, v1);
            if (!lane) { g_gh1[r0] = v0 + bhh1[r0]; g_gh1[r0 + 1] = v1 + bhh1[r0 + 1]; }
        }
    }
    gsync();   // barrier 1

    // ---------- phase 2: h0 recompute (local); gi1 = W_ih1 @ h0 ----------
    {
        float r_ = sigmoidf_(g_gi0[t] + g_gh0[t]);
        float z  = sigmoidf_(g_gi0[H + t] + g_gh0[H + t]);
        float n  = tanhf(g_gi0[2 * H + t] + r_ * g_gh0[2 * H + t]);
        float h  = (1.f - z) * n + z * sh_lh[t];
        sh_h0[t] = h;
        if (b == 0) out[V + H + t] = h;   // hidden[0]
    }
    __syncthreads();
    if (gw < 1536) {
        int r0 = 2 * gw;
        float v0, v1;
        wdot2((const float4*)(Wih1 + (size_t)r0 * H),
              (const float4*)(Wih1 + (size_t)(r0 + 1) * H),
              (const float4*)sh_h0, 256, lane, v0, v1);
        if (!lane) { g_gi1[r0] = v0 + bih1[r0]; g_gi1[r0 + 1] = v1 + bih1[r0 + 1]; }
    }
    gsync();   // barrier 2

    // ---------- phase 3: h1 recompute (local); v partials -----------------
    {
        float r_ = sigmoidf_(g_gi1[t] + g_gh1[t]);
        float z  = sigmoidf_(g_gi1[H + t] + g_gh1[H + t]);
        float n  = tanhf(g_gi1[2 * H + t] + r_ * g_gh1[2 * H + t]);
        float h  = (1.f - z) * n + z * sh_lh[H + t];
        sh_xcat[t] = h;
        if (b == 0) out[V + 2 * H + t] = h; // hidden[1]
    }
    __syncthreads();
    {
        float acc = 0.f;
        int i0 = b * ICH;
#pragma unroll
        for (int k = 0; k < ICH; k++) {
            int i = i0 + k;
            if (i < H) acc = fmaf(Wattn[(size_t)i * H + t], sh_xcat[i], acc);
        }
        atomicAdd(&g_v[t], acc);
    }
    gsync();   // barrier 3

    // ---------- phase 4: energies ----------------------------------------
    sh_h0[t] = g_v[t];
    __syncthreads();
    if (gw < S) {
        float s = wdot((const float4*)(enc + (size_t)gw * H),
                       (const float4*)sh_h0, 256, lane);
        if (!lane) g_energ[gw] = s;
    }
    gsync();   // barrier 4

    // ---------- phase 5: softmax (redundant) + ctx partials ---------------
    {
        float m = -INFINITY;
        for (int i = t; i < S; i += NT) m = fmaxf(m, g_energ[i]);
#pragma unroll
        for (int o = 16; o; o >>= 1) m = fmaxf(m, __shfl_xor_sync(0xffffffffu, m, o));
        if (!lane) sh_red[wid] = m;
        __syncthreads();
        if (wid == 0) {
            m = sh_red[lane];
#pragma unroll
            for (int o = 16; o; o >>= 1) m = fmaxf(m, __shfl_xor_sync(0xffffffffu, m, o));
            if (!lane) sh_bc[0] = m;
        }
        __syncthreads();
        float bmax = sh_bc[0];
        float sum = 0.f;
        for (int i = t; i < S; i += NT) sum += __expf(g_energ[i] - bmax);
#pragma unroll
        for (int o = 16; o; o >>= 1) sum += __shfl_xor_sync(0xffffffffu, sum, o);
        if (!lane) sh_red[wid] = sum;
        __syncthreads();
        if (wid == 0) {
            sum = sh_red[lane];
#pragma unroll
            for (int o = 16; o; o >>= 1) sum += __shfl_xor_sync(0xffffffffu, sum, o);
            if (!lane) sh_bc[1] = sum;
        }
        __syncthreads();
        float inv = 1.f / sh_bc[1];
        int s0 = b * SCH;
        if (t < SCH && s0 + t < S) {
            float a = __expf(g_energ[s0 + t] - bmax) * inv;
            sh_a[t] = a;
            out[V + 3 * H + s0 + t] = a;  // attn_weights
        }
        __syncthreads();
        float acc = 0.f;
#pragma unroll
        for (int k = 0; k < SCH; k++) {
            int s = s0 + k;
            if (s < S) acc = fmaf(sh_a[k], enc[(size_t)s * H + t], acc);
        }
        atomicAdd(&g_ctx[t], acc);
    }
    gsync();   // barrier 5

    // ---------- phase 6: logits (412 MB, 8-row register blocking) ---------
    sh_xcat[H + t] = g_ctx[t];
    if (b == 0) out[V + t] = g_ctx[t];    // context
    __syncthreads();
    const int base = b * ROWS_PB;
    const int nrows = min(ROWS_PB, V - base);
    for (int rl = wid * 8; rl < nrows; rl += 256) {
        // rows rl..rl+7, clamped for loads; stores guarded
        int rmax = nrows - 1;
        const float4* wp[8];
#pragma unroll
        for (int k = 0; k < 8; k++) {
            int r = base + min(rl + k, rmax);
            wp[k] = (const float4*)(Wout + (size_t)r * 2 * H);
        }
        float s[8];
        wdot8(wp[0], wp[1], wp[2], wp[3], wp[4], wp[5], wp[6], wp[7],
              (const float4*)sh_xcat, 512, lane, s);
        if (!lane) {
#pragma unroll
            for (int k = 0; k < 8; k++) {
                int rr = rl + k;
                if (rr < nrows) sh_logit[rr] = s[k] + bout[base + rr];
            }
        }
    }
    __syncthreads();
    {
        float m = -INFINITY;
        for (int i = t; i < nrows; i += NT) m = fmaxf(m, sh_logit[i]);
#pragma unroll
        for (int o = 16; o; o >>= 1) m = fmaxf(m, __shfl_xor_sync(0xffffffffu, m, o));
        if (!lane) sh_red[wid] = m;
        __syncthreads();
        if (wid == 0) {
            m = sh_red[lane];
#pragma unroll
            for (int o = 16; o; o >>= 1) m = fmaxf(m, __shfl_xor_sync(0xffffffffu, m, o));
            if (!lane) sh_bc[0] = m;
        }
        __syncthreads();
        float bmax = sh_bc[0];
        float sum = 0.f;
        for (int i = t; i < nrows; i += NT) sum += __expf(sh_logit[i] - bmax);
#pragma unroll
        for (int o = 16; o; o >>= 1) sum += __shfl_xor_sync(0xffffffffu, sum, o);
        if (!lane) sh_red[wid] = sum;
        __syncthreads();
        if (wid == 0) {
            sum = sh_red[lane];
#pragma unroll
            for (int o = 16; o; o >>= 1) sum += __shfl_xor_sync(0xffffffffu, sum, o);
            if (!lane) { g_part[2 * b] = bmax; g_part[2 * b + 1] = sum; }
        }
    }
    gsync();   // barrier 6

    // ---------- phase 7: merge LSE; write log_softmax ---------------------
    {
        if (wid == 0) {
            float m = -INFINITY, sacc = 0.f;
            for (int i = lane; i < NB; i += 32) {
                float mi = g_part[2 * i], si = g_part[2 * i + 1];
                float mn = fmaxf(m, mi);
                sacc = sacc * __expf(m - mn) + si * __expf(mi - mn);
                m = mn;
            }
#pragma unroll
            for (int o = 16; o; o >>= 1) {
                float mo = __shfl_xor_sync(0xffffffffu, m, o);
                float so = __shfl_xor_sync(0xffffffffu, sacc, o);
                float mn = fmaxf(m, mo);
                sacc = sacc * __expf(m - mn) + so * __expf(mo - mn);
                m = mn;
            }
            if (!lane) { sh_bc[0] = m; sh_bc[1] = logf(sacc); }
        }
        __syncthreads();
        float mm = sh_bc[0], ls = sh_bc[1];
        for (int i = t; i < nrows; i += NT)
            out[base + i] = sh_logit[i] - mm - ls;
    }
}

// ---------------- launch ----------------
extern "C" void kernel_launch(void* const* d_in, const int* in_sizes, int n_in,
                              void* d_out, int out_size) {
    const int*   word  = (const int*)  d_in[0];
    const float* lctx  = (const float*)d_in[1];
    const float* lh    = (const float*)d_in[2];
    const float* enc   = (const float*)d_in[3];
    const float* emb   = (const float*)d_in[4];
    const float* Wih0  = (const float*)d_in[5];
    const float* Whh0  = (const float*)d_in[6];
    const float* bih0  = (const float*)d_in[7];
    const float* bhh0  = (const float*)d_in[8];
    const float* Wih1  = (const float*)d_in[9];
    const float* Whh1  = (const float*)d_in[10];
    const float* bih1  = (const float*)d_in[11];
    const float* bhh1  = (const float*)d_in[12];
    const float* Wattn = (const float*)d_in[13];
    // d_in[14] = b_attn: cancels in softmax
    const float* Wout  = (const float*)d_in[15];
    const float* bout  = (const float*)d_in[16];
    float* out = (float*)d_out;

    decoder_kernel<<<NB, NT>>>(word, lctx, lh, enc, emb,
                               Wih0, Whh0, bih0, bhh0,
                               Wih1, Whh1, bih1, bhh1,
                               Wattn, Wout, bout, out);
}

// round 12
// speedup vs baseline: 1.2951x; 1.2116x over previous
#include <cuda_runtime.h>
#include <math.h>

#define H    1024
#define V    50257
#define S    4096
#define G3   3072
#define NB   148
#define NT   1024
#define NWARP (NB * 32)
#define ROWS_PB 340            // ceil(V/NB) for the final write pass
#define SCH 28                 // ceil(S/NB)
#define ICH 7                  // ceil(H/NB)
#define NTILES6 1571           // ceil(V/32) logits tiles

// ---------------- global scratch ----------------
__device__ float g_gi0[G3];
__device__ float g_gh0[G3];
__device__ float g_gi1[G3];
__device__ float g_gh1[G3];
__device__ float g_v[H];
__device__ float g_energ[S];
__device__ float g_ctx[H];
__device__ float g_logits[V + 32];
__device__ float g_part[2 * NB];
__device__ unsigned g_q;
__device__ unsigned g_count;
__device__ volatile unsigned g_epoch;

// ---------------- software grid barrier ----------------
__device__ __forceinline__ void gsync() {
    __syncthreads();
    if (threadIdx.x == 0) {
        __threadfence();
        unsigned e = g_epoch;
        if (atomicAdd(&g_count, 1) == (unsigned)(gridDim.x - 1)) {
            g_count = 0;
            __threadfence();
            g_epoch = e + 1;
        } else {
            while (g_epoch == e) __nanosleep(32);
        }
        __threadfence();
    }
    __syncthreads();
}

__device__ __forceinline__ float sigmoidf_(float x) {
    return 1.f / (1.f + __expf(-x));
}

// warp dot, 4 streams; CS=true -> evict-first loads for single-use weights
template<bool CS>
__device__ __forceinline__ float wdot(const float4* __restrict__ w,
                                      const float4* __restrict__ x,
                                      int n4, int lane) {
    float s0 = 0.f, s1 = 0.f, s2 = 0.f, s3 = 0.f;
#pragma unroll 4
    for (int i = lane; i < n4; i += 128) {
        float4 a0 = CS ? __ldcs(w + i)      : __ldg(w + i);
        float4 a1 = CS ? __ldcs(w + i + 32) : __ldg(w + i + 32);
        float4 a2 = CS ? __ldcs(w + i + 64) : __ldg(w + i + 64);
        float4 a3 = CS ? __ldcs(w + i + 96) : __ldg(w + i + 96);
        float4 b0 = x[i];
        float4 b1 = x[i + 32];
        float4 b2 = x[i + 64];
        float4 b3 = x[i + 96];
        s0 = fmaf(a0.x, b0.x, fmaf(a0.y, b0.y, fmaf(a0.z, b0.z, fmaf(a0.w, b0.w, s0))));
        s1 = fmaf(a1.x, b1.x, fmaf(a1.y, b1.y, fmaf(a1.z, b1.z, fmaf(a1.w, b1.w, s1))));
        s2 = fmaf(a2.x, b2.x, fmaf(a2.y, b2.y, fmaf(a2.z, b2.z, fmaf(a2.w, b2.w, s2))));
        s3 = fmaf(a3.x, b3.x, fmaf(a3.y, b3.y, fmaf(a3.z, b3.z, fmaf(a3.w, b3.w, s3))));
    }
    float s = (s0 + s1) + (s2 + s3);
#pragma unroll
    for (int o = 16; o; o >>= 1) s += __shfl_xor_sync(0xffffffffu, s, o);
    return s;
}

__global__ void __launch_bounds__(NT, 1)
decoder_kernel(const int* __restrict__ word, const float* __restrict__ lctx,
               const float* __restrict__ lh, const float* __restrict__ enc,
               const float* __restrict__ emb,
               const float* __restrict__ Wih0, const float* __restrict__ Whh0,
               const float* __restrict__ bih0, const float* __restrict__ bhh0,
               const float* __restrict__ Wih1, const float* __restrict__ Whh1,
               const float* __restrict__ bih1, const float* __restrict__ bhh1,
               const float* __restrict__ Wattn, const float* __restrict__ Wout,
               const float* __restrict__ bout, float* __restrict__ out) {
    __shared__ float sh_in[2 * H];
    __shared__ float sh_lh[2 * H];
    __shared__ float sh_h0[H];            // h0; later stages v
    __shared__ float sh_xcat[2 * H];      // [h1 ; ctx]
    __shared__ float sh_a[SCH];
    __shared__ float sh_red[32];
    __shared__ float sh_red2[32];
    __shared__ float sh_bc[2];
    __shared__ int   sh_tile;

    const int t = threadIdx.x;
    const int lane = t & 31;
    const int wid = t >> 5;
    const int b = blockIdx.x;
    const int gw = b * 32 + wid;

    {
        int w0 = word[0];
        sh_in[t]     = emb[(size_t)w0 * H + t];
        sh_in[H + t] = lctx[t];
        sh_lh[t]     = lh[t];
        sh_lh[H + t] = lh[H + t];
    }
    if (b == 0) {
        g_v[t] = 0.f;
        g_ctx[t] = 0.f;
        if (t == 0) g_q = 0;
    }
    __syncthreads();

    // ---------- phase 1: equal 12KB units, one pass ----------------------
    // units 0..3071:   gi0 row u (8KB) + gh0 row u (4KB)
    // units 3072..4095: gh1 rows 3k,3k+1,3k+2 (3 x 4KB)
    if (gw < G3) {
        float s = wdot<true>((const float4*)(Wih0 + (size_t)gw * 2 * H),
                             (const float4*)sh_in, 512, lane);
        if (!lane) g_gi0[gw] = s + bih0[gw];
        float s2 = wdot<true>((const float4*)(Whh0 + (size_t)gw * H),
                              (const float4*)sh_lh, 256, lane);
        if (!lane) g_gh0[gw] = s2 + bhh0[gw];
    } else if (gw < 4096) {
        int r0 = 3 * (gw - G3);
#pragma unroll
        for (int j = 0; j < 3; j++) {
            int r = r0 + j;
            float s = wdot<true>((const float4*)(Whh1 + (size_t)r * H),
                                 (const float4*)(sh_lh + H), 256, lane);
            if (!lane) g_gh1[r] = s + bhh1[r];
        }
    }
    gsync();   // barrier 1

    // ---------- phase 2: h0 recompute (local); gi1 = W_ih1 @ h0 ----------
    {
        float r_ = sigmoidf_(g_gi0[t] + g_gh0[t]);
        float z  = sigmoidf_(g_gi0[H + t] + g_gh0[H + t]);
        float n  = tanhf(g_gi0[2 * H + t] + r_ * g_gh0[2 * H + t]);
        float h  = (1.f - z) * n + z * sh_lh[t];
        sh_h0[t] = h;
        if (b == 0) out[V + H + t] = h;   // hidden[0]
    }
    __syncthreads();
    if (gw < G3) {
        float s = wdot<true>((const float4*)(Wih1 + (size_t)gw * H),
                             (const float4*)sh_h0, 256, lane);
        if (!lane) g_gi1[gw] = s + bih1[gw];
    }
    gsync();   // barrier 2

    // ---------- phase 3: h1 recompute (local); v partials -----------------
    {
        float r_ = sigmoidf_(g_gi1[t] + g_gh1[t]);
        float z  = sigmoidf_(g_gi1[H + t] + g_gh1[H + t]);
        float n  = tanhf(g_gi1[2 * H + t] + r_ * g_gh1[2 * H + t]);
        float h  = (1.f - z) * n + z * sh_lh[H + t];
        sh_xcat[t] = h;
        if (b == 0) out[V + 2 * H + t] = h; // hidden[1]
    }
    __syncthreads();
    {
        float acc = 0.f;
        int i0 = b * ICH;
#pragma unroll
        for (int k = 0; k < ICH; k++) {
            int i = i0 + k;
            if (i < H) acc = fmaf(Wattn[(size_t)i * H + t], sh_xcat[i], acc);
        }
        atomicAdd(&g_v[t], acc);
    }
    gsync();   // barrier 3

    // ---------- phase 4: energies (enc stays L2-resident: no .cs) ---------
    sh_h0[t] = g_v[t];
    __syncthreads();
    if (gw < S) {
        float s = wdot<false>((const float4*)(enc + (size_t)gw * H),
                              (const float4*)sh_h0, 256, lane);
        if (!lane) g_energ[gw] = s;
    }
    gsync();   // barrier 4

    // ---------- phase 5: softmax (redundant) + ctx partials ---------------
    {
        float m = -INFINITY;
        for (int i = t; i < S; i += NT) m = fmaxf(m, g_energ[i]);
#pragma unroll
        for (int o = 16; o; o >>= 1) m = fmaxf(m, __shfl_xor_sync(0xffffffffu, m, o));
        if (!lane) sh_red[wid] = m;
        __syncthreads();
        if (wid == 0) {
            m = sh_red[lane];
#pragma unroll
            for (int o = 16; o; o >>= 1) m = fmaxf(m, __shfl_xor_sync(0xffffffffu, m, o));
            if (!lane) sh_bc[0] = m;
        }
        __syncthreads();
        float bmax = sh_bc[0];
        float sum = 0.f;
        for (int i = t; i < S; i += NT) sum += __expf(g_energ[i] - bmax);
#pragma unroll
        for (int o = 16; o; o >>= 1) sum += __shfl_xor_sync(0xffffffffu, sum, o);
        if (!lane) sh_red[wid] = sum;
        __syncthreads();
        if (wid == 0) {
            sum = sh_red[lane];
#pragma unroll
            for (int o = 16; o; o >>= 1) sum += __shfl_xor_sync(0xffffffffu, sum, o);
            if (!lane) sh_bc[1] = sum;
        }
        __syncthreads();
        float inv = 1.f / sh_bc[1];
        int s0 = b * SCH;
        if (t < SCH && s0 + t < S) {
            float a = __expf(g_energ[s0 + t] - bmax) * inv;
            sh_a[t] = a;
            out[V + 3 * H + s0 + t] = a;  // attn_weights
        }
        __syncthreads();
        float acc = 0.f;
#pragma unroll
        for (int k = 0; k < SCH; k++) {
            int s = s0 + k;
            if (s < S) acc = fmaf(sh_a[k], enc[(size_t)s * H + t], acc);
        }
        atomicAdd(&g_ctx[t], acc);
    }
    gsync();   // barrier 5

    // ---------- phase 6: logits via work-stealing queue + online LSE ------
    sh_xcat[H + t] = g_ctx[t];
    if (b == 0) out[V + t] = g_ctx[t];    // context
    __syncthreads();
    float lm = -INFINITY, lsum = 0.f;     // identical across lanes of a warp
    for (;;) {
        if (t == 0) sh_tile = (int)atomicAdd(&g_q, 1u);
        __syncthreads();
        int tile = sh_tile;
        __syncthreads();
        if (tile >= NTILES6) break;
        int r = tile * 32 + wid;
        if (r < V) {
            float s = wdot<true>((const float4*)(Wout + (size_t)r * 2 * H),
                                 (const float4*)sh_xcat, 512, lane) + bout[r];
            if (!lane) g_logits[r] = s;
            float mn = fmaxf(lm, s);
            lsum = lsum * __expf(lm - mn) + __expf(s - mn);
            lm = mn;
        }
    }
    // block-level (max,sum) merge over 32 warps
    if (!lane) { sh_red[wid] = lm; sh_red2[wid] = lsum; }
    __syncthreads();
    if (wid == 0) {
        float m = sh_red[lane], sacc = sh_red2[lane];
#pragma unroll
        for (int o = 16; o; o >>= 1) {
            float mo = __shfl_xor_sync(0xffffffffu, m, o);
            float so = __shfl_xor_sync(0xffffffffu, sacc, o);
            float mn = fmaxf(m, mo);
            sacc = sacc * __expf(m - mn) + so * __expf(mo - mn);
            m = mn;
        }
        if (!lane) { g_part[2 * b] = m; g_part[2 * b + 1] = sacc; }
    }
    gsync();   // barrier 6

    // ---------- phase 7: merge LSE (redundant); write log_softmax ---------
    {
        if (wid == 0) {
            float m = -INFINITY, sacc = 0.f;
            for (int i = lane; i < NB; i += 32) {
                float mi = g_part[2 * i], si = g_part[2 * i + 1];
                float mn = fmaxf(m, mi);
                sacc = sacc * __expf(m - mn) + si * __expf(mi - mn);
                m = mn;
            }
#pragma unroll
            for (int o = 16; o; o >>= 1) {
                float mo = __shfl_xor_sync(0xffffffffu, m, o);
                float so = __shfl_xor_sync(0xffffffffu, sacc, o);
                float mn = fmaxf(m, mo);
                sacc = sacc * __expf(m - mn) + so * __expf(mo - mn);
                m = mn;
            }
            if (!lane) { sh_bc[0] = m; sh_bc[1] = logf(sacc); }
        }
        __syncthreads();
        float mm = sh_bc[0], ls = sh_bc[1];
        const int base = b * ROWS_PB;
        const int nrows = min(ROWS_PB, V - base);
        for (int i = t; i < nrows; i += NT)
            out[base + i] = g_logits[base + i] - mm - ls;
    }
}

// ---------------- launch ----------------
extern "C" void kernel_launch(void* const* d_in, const int* in_sizes, int n_in,
                              void* d_out, int out_size) {
    const int*   word  = (const int*)  d_in[0];
    const float* lctx  = (const float*)d_in[1];
    const float* lh    = (const float*)d_in[2];
    const float* enc   = (const float*)d_in[3];
    const float* emb   = (const float*)d_in[4];
    const float* Wih0  = (const float*)d_in[5];
    const float* Whh0  = (const float*)d_in[6];
    const float* bih0  = (const float*)d_in[7];
    const float* bhh0  = (const float*)d_in[8];
    const float* Wih1  = (const float*)d_in[9];
    const float* Whh1  = (const float*)d_in[10];
    const float* bih1  = (const float*)d_in[11];
    const float* bhh1  = (const float*)d_in[12];
    const float* Wattn = (const float*)d_in[13];
    // d_in[14] = b_attn: cancels in softmax
    const float* Wout  = (const float*)d_in[15];
    const float* bout  = (const float*)d_in[16];
    float* out = (float*)d_out;

    decoder_kernel<<<NB, NT>>>(word, lctx, lh, enc, emb,
                               Wih0, Whh0, bih0, bhh0,
                               Wih1, Whh1, bih1, bhh1,
                               Wattn, Wout, bout, out);
}